// round 1
// baseline (speedup 1.0000x reference)
#include <cuda_runtime.h>
#include <math.h>

// Problem shapes (fixed by setup_inputs)
#define NB 2
#define NF 2
#define NX 256
#define NY 256
#define NZ 16
#define NR 24
#define NBF (NB*NF)
#define NOUT (NBF*NR*NZ)   // 1536

#define XT 4               // xi rows per block -> grid.x = 64, grid.y = 4 -> 256 blocks

// Folded constants:
//   arg_to_exp2 = -(50*log2e) * ((pi/12)*du)^2 = -(S*du)^2,  S = sqrt(50*log2e)*pi/12
//   v = theta*K1 + K2,  K1 = sqrt(50*log2e) = 8.4932180,  K2 = 12*S,  W = 24*S
#define K1C 8.4932180f
#define SC  2.2235193f
#define K2C 26.6822312f
#define WC  53.3644625f

__global__ void gre_zero_kernel(float* __restrict__ out) {
    int i = blockIdx.x * blockDim.x + threadIdx.x;
    if (i < NOUT) out[i] = 0.0f;
}

__global__ void gre_finalize_kernel(float* __restrict__ out) {
    int i = blockIdx.x * blockDim.x + threadIdx.x;
    // 2 * coef, coef = 1/(0.1*sqrt(2*pi)) = 3.98942280401
    const float TWO_COEF = 7.9788456080286535f;
    if (i < NOUT) out[i] = sqrtf(TWO_COEF * out[i]);
}

__global__ __launch_bounds__(256)
void gre_accum_kernel(const float* __restrict__ x,
                      const float* __restrict__ com_r,
                      const float* __restrict__ com_i,
                      float* __restrict__ out) {
    const int bf    = blockIdx.y;          // 0..3
    const int xbase = blockIdx.x * XT;     // row tile
    const int tid   = threadIdx.x;         // 256
    const int z     = tid & 15;
    const int ylane = tid >> 4;            // 0..15

    const float cr = com_r[bf * NZ + z];   // column center (real axis)
    const float ci = com_i[bf * NZ + z];   // row center (imag axis)

    float acc[NR];
    #pragma unroll
    for (int r = 0; r < NR; r++) acc[r] = 0.0f;

    const float* xb = x + ((size_t)bf * NX * NY + (size_t)xbase * NY) * NZ;

    for (int xl = 0; xl < XT; xl++) {
        const float dyv = (float)(xbase + xl) - ci;   // imag component
        const float ay  = fabsf(dyv);
        const float* xrow = xb + (size_t)xl * NY * NZ;

        #pragma unroll 4
        for (int yo = 0; yo < NY / 16; yo++) {
            const int   yi  = yo * 16 + ylane;
            const float dxv = (float)yi - cr;         // real component
            const float xv  = xrow[yo * 256 + tid];   // fully coalesced

            // ---- custom atan2(dyv, dxv) ----
            float ax = fabsf(dxv);
            float mx = fmaxf(ax, ay);
            float mn = fminf(ax, ay);
            float t  = __fdividef(mn, mx);            // t in [0,1]
            float t2 = t * t;
            float p  = fmaf(t2, -0.0117212f, 0.05265332f);
            p = fmaf(t2, p, -0.11643287f);
            p = fmaf(t2, p,  0.19354346f);
            p = fmaf(t2, p, -0.33262347f);
            p = fmaf(t2, p,  0.99997726f);
            float a = t * p;
            if (ay > ax)   a = 1.5707963267948966f - a;
            if (dxv < 0.f) a = 3.1415926535897932f - a;
            a = copysignf(a, dyv);                    // theta = atan2(dy, dx)

            // scaled angular coordinate: v = (theta + pi) * (12/pi) * S
            const float v = fmaf(a, K1C, K2C);

            #pragma unroll
            for (int r = 0; r < NR; r++) {
                float d0 = v - (float)r * SC;             // folded to immediate
                float ad = fabsf(d0);
                float d  = fminf(ad, WC - ad);            // circular wrap
                float arg = -d * d;                       // = -(50*log2e)*dtheta^2
                float w;
                asm("ex2.approx.ftz.f32 %0, %1;" : "=f"(w) : "f"(arg));
                acc[r] = fmaf(w, xv, acc[r]);
            }
        }
    }

    // ---- reduction: sum over ylane (threads with same z) ----
    // warp layout: lanes 0-15 = (even ylane, z=0..15), lanes 16-31 = (odd ylane)
    #pragma unroll
    for (int r = 0; r < NR; r++)
        acc[r] += __shfl_down_sync(0xffffffffu, acc[r], 16);

    __shared__ float sm[8][16][NR];   // 12 KB
    const int wid  = tid >> 5;
    const int lane = tid & 31;
    if (lane < 16) {
        #pragma unroll
        for (int r = 0; r < NR; r++) sm[wid][lane][r] = acc[r];
    }
    __syncthreads();

    for (int p = tid; p < 16 * NR; p += 256) {
        const int zz = p & 15;
        const int rr = p >> 4;
        float sum = 0.0f;
        #pragma unroll
        for (int w8 = 0; w8 < 8; w8++) sum += sm[w8][zz][rr];
        atomicAdd(&out[(bf * NR + rr) * NZ + zz], sum);
    }
}

extern "C" void kernel_launch(void* const* d_in, const int* in_sizes, int n_in,
                              void* d_out, int out_size) {
    const float* x     = (const float*)d_in[0];
    const float* com_r = (const float*)d_in[1];
    const float* com_i = (const float*)d_in[2];
    float* out = (float*)d_out;

    gre_zero_kernel<<<(NOUT + 255) / 256, 256>>>(out);

    dim3 grid(NX / XT, NBF);
    gre_accum_kernel<<<grid, 256>>>(x, com_r, com_i, out);

    gre_finalize_kernel<<<(NOUT + 255) / 256, 256>>>(out);
}

// round 2
// speedup vs baseline: 1.6044x; 1.6044x over previous
#include <cuda_runtime.h>
#include <math.h>

// Problem shapes (fixed by setup_inputs)
#define NB 2
#define NF 2
#define NX 256
#define NY 256
#define NZ 16
#define NR 24
#define NBF (NB*NF)
#define NOUT (NBF*NR*NZ)   // 1536

#define XT 4               // x rows per block -> grid = (64, 4)
#define NBLK (NX/XT)       // 64 blocks per bf

// S = sqrt(50*log2(e)) * (pi/12): arg for ex2 is -(S*(du-k))^2
#define SC  2.2235193f

// Per-block partial sums: [bf][blockX][r][z] — every slot written, no init needed.
__device__ float g_partial[NBF * NBLK * NR * NZ];

__global__ __launch_bounds__(256)
void gre_accum_kernel(const float* __restrict__ x,
                      const float* __restrict__ com_r,
                      const float* __restrict__ com_i) {
    __shared__ float sm[29][256];      // bins -2..26 (padded), per-thread column

    const int bf    = blockIdx.y;      // 0..3
    const int xbase = blockIdx.x * XT;
    const int tid   = threadIdx.x;     // 256
    const int z     = tid & 15;
    const int ylane = tid >> 4;        // 0..15

    // zero shared accumulators
    #pragma unroll
    for (int i = 0; i < 29; i++) sm[i][tid] = 0.0f;
    __syncthreads();

    const float cr = com_r[bf * NZ + z];   // column center (real axis)
    const float ci = com_i[bf * NZ + z];   // row center (imag axis)

    float* colp = &sm[2][tid];             // row r0+2 base, per-thread column

    const float* xb = x + ((size_t)bf * NX * NY + (size_t)xbase * NY) * NZ;

    for (int xl = 0; xl < XT; xl++) {
        const float dyv = (float)(xbase + xl) - ci;   // imag component
        const float ay  = fabsf(dyv);
        const float* xrow = xb + (size_t)xl * NY * NZ;

        #pragma unroll 4
        for (int yo = 0; yo < NY / 16; yo++) {
            const int   yi  = yo * 16 + ylane;
            const float dxv = (float)yi - cr;         // real component
            const float xv  = xrow[yo * 256 + tid];   // fully coalesced

            // ---- custom atan2(dyv, dxv) ----
            float ax = fabsf(dxv);
            float mx = fmaxf(fmaxf(ax, ay), 1e-30f);
            float mn = fminf(ax, ay);
            float t  = __fdividef(mn, mx);            // t in [0,1]
            float t2 = t * t;
            float p  = fmaf(t2, -0.0117212f, 0.05265332f);
            p = fmaf(t2, p, -0.11643287f);
            p = fmaf(t2, p,  0.19354346f);
            p = fmaf(t2, p, -0.33262347f);
            p = fmaf(t2, p,  0.99997726f);
            float a = t * p;
            if (ay > ax)   a = 1.5707963267948966f - a;
            if (dxv < 0.f) a = 3.1415926535897932f - a;
            a = copysignf(a, dyv);                    // theta = atan2(dy, dx)

            // bin coordinate: u = (theta + pi) * 12/pi  in (0, 24]
            const float uu  = fmaf(a, 3.8197186342054880f, 12.0f);
            const float r0f = rintf(uu);
            const float du  = uu - r0f;               // in [-0.5, 0.5]
            const int   r0  = (int)r0f;               // 0..24
            const float ts  = du * SC;

            float* pacc = colp + r0 * 256;            // row (r0+2), this column

            // 5 nearest bins: k = -2..2  (immediate smem offsets)
            #pragma unroll
            for (int k = -2; k <= 2; k++) {
                float d = ts - (float)k * SC;
                float arg = -d * d;
                float w;
                asm("ex2.approx.ftz.f32 %0, %1;" : "=f"(w) : "f"(arg));
                pacc[k * 256] = fmaf(w, xv, pacc[k * 256]);
            }
        }
    }

    __syncthreads();

    // ---- block reduction: fold 29 rows -> 24 bins, sum 16 y-columns per z ----
    float* gp = g_partial + ((bf * NBLK + blockIdx.x) * NR) * NZ;
    for (int p = tid; p < NR * NZ; p += 256) {
        const int zz = p & 15;
        const int rr = p >> 4;          // bin 0..23
        float s = 0.0f;
        #pragma unroll
        for (int j = 0; j < 16; j++) s += sm[rr + 2][zz + 16 * j];
        if (rr < 3) {                   // logical bins 24,25,26 -> 0,1,2
            #pragma unroll
            for (int j = 0; j < 16; j++) s += sm[rr + 26][zz + 16 * j];
        }
        if (rr >= 22) {                 // logical bins -2,-1 -> 22,23
            #pragma unroll
            for (int j = 0; j < 16; j++) s += sm[rr - 22][zz + 16 * j];
        }
        gp[rr * NZ + zz] = s;
    }
}

__global__ void gre_finalize_kernel(float* __restrict__ out) {
    const int i = blockIdx.x * blockDim.x + threadIdx.x;   // 0..1535
    if (i >= NOUT) return;
    const int bf = i / (NR * NZ);
    const int rz = i % (NR * NZ);
    const float* p = g_partial + (size_t)bf * NBLK * NR * NZ + rz;
    float s = 0.0f;
    #pragma unroll 8
    for (int b = 0; b < NBLK; b++) s += p[b * NR * NZ];
    // out = sqrt(2 * coef * s), coef = 1/(0.1*sqrt(2*pi))
    out[i] = sqrtf(7.9788456080286535f * s);
}

extern "C" void kernel_launch(void* const* d_in, const int* in_sizes, int n_in,
                              void* d_out, int out_size) {
    const float* x     = (const float*)d_in[0];
    const float* com_r = (const float*)d_in[1];
    const float* com_i = (const float*)d_in[2];
    float* out = (float*)d_out;

    dim3 grid(NBLK, NBF);
    gre_accum_kernel<<<grid, 256>>>(x, com_r, com_i);
    gre_finalize_kernel<<<(NOUT + 255) / 256, 256>>>(out);
}

// round 3
// speedup vs baseline: 1.9211x; 1.1974x over previous
#include <cuda_runtime.h>
#include <math.h>

// Problem shapes (fixed by setup_inputs)
#define NB 2
#define NF 2
#define NX 256
#define NY 256
#define NZ 16
#define NR 24
#define NBF (NB*NF)
#define NOUT (NBF*NR*NZ)   // 1536

#define XT 2               // x rows per block -> grid = (128, 4) = 512 blocks
#define NBLK (NX/XT)       // 128 partial blocks per bf

// SC = sqrt(50*log2(e)) * (pi/12)  (bin spacing in ex2-scaled units)
#define SC   2.2235193f
// c1  = 2^(-SC^2),  c21 = 2^(-3*SC^2)
#define C1C  0.032489281f
#define C21C 3.4233397e-5f

// Per-block partials, transposed: [out_idx][block]  (out_idx = (bf*NR+r)*NZ+z)
__device__ float g_partial[NOUT * NBLK];

__global__ __launch_bounds__(256)
void gre_accum_kernel(const float* __restrict__ x,
                      const float* __restrict__ com_r,
                      const float* __restrict__ com_i) {
    __shared__ float sm[28][256];      // rows store bins -1..26 (row i = bin i-1)

    const int bf    = blockIdx.y;      // 0..3
    const int xbase = blockIdx.x * XT;
    const int tid   = threadIdx.x;     // 256
    const int z     = tid & 15;
    const int ylane = tid >> 4;        // 0..15

    #pragma unroll
    for (int i = 0; i < 28; i++) sm[i][tid] = 0.0f;
    __syncthreads();

    const float cr = com_r[bf * NZ + z];   // column center (real axis)
    const float ci = com_i[bf * NZ + z];   // row center (imag axis)

    float* col0 = &sm[0][tid];

    const float* xb = x + ((size_t)bf * NX * NY + (size_t)xbase * NY) * NZ;

    for (int xl = 0; xl < XT; xl++) {
        const float dyv = (float)(xbase + xl) - ci;   // imag component
        const float ay  = fabsf(dyv);
        const float* xrow = xb + (size_t)xl * NY * NZ;

        #pragma unroll 4
        for (int yo = 0; yo < NY / 16; yo++) {
            const int   yi  = yo * 16 + ylane;
            const float dxv = (float)yi - cr;         // real component
            const float xv  = xrow[yo * 256 + tid];   // fully coalesced

            // ---- custom atan2(dyv, dxv) ----
            float ax = fabsf(dxv);
            float mx = fmaxf(fmaxf(ax, ay), 1e-30f);
            float mn = fminf(ax, ay);
            float t  = __fdividef(mn, mx);            // t in [0,1]
            float t2 = t * t;
            float p  = fmaf(t2, -0.0117212f, 0.05265332f);
            p = fmaf(t2, p, -0.11643287f);
            p = fmaf(t2, p,  0.19354346f);
            p = fmaf(t2, p, -0.33262347f);
            p = fmaf(t2, p,  0.99997726f);
            float a = t * p;
            if (ay > ax)   a = 1.5707963267948966f - a;
            if (dxv < 0.f) a = 3.1415926535897932f - a;
            a = copysignf(a, dyv);                    // theta = atan2(dy, dx)

            // bin coordinate: u = (theta + pi) * 12/pi in (0, 24]
            const float uu  = fmaf(a, 3.8197186342054880f, 12.0f);
            const float r0f = floorf(uu);
            const float du  = uu - r0f;               // in [0, 1)
            const int   r0  = (int)r0f;               // 0..24
            const float ts  = du * SC;

            // 4 nearest bins (k = -1..2): w_k = E1 * P^k * 2^(-k^2*SC^2)
            const float q = ts * (2.0f * SC);
            float E1, P, R;
            asm("ex2.approx.ftz.f32 %0, %1;" : "=f"(E1) : "f"(-ts * ts));
            asm("ex2.approx.ftz.f32 %0, %1;" : "=f"(P)  : "f"(q));
            asm("ex2.approx.ftz.f32 %0, %1;" : "=f"(R)  : "f"(-q));

            const float w0  = E1;                     // k = 0
            const float w1  = E1 * (P * C1C);         // k = 1
            const float w2  = w1 * (P * C21C);        // k = 2
            const float wm1 = E1 * (R * C1C);         // k = -1

            // row r0 + k + 1, k = -1..2 -> rows r0 .. r0+3 (imm offsets)
            float* pacc = col0 + r0 * 256;
            pacc[0]   = fmaf(wm1, xv, pacc[0]);
            pacc[256] = fmaf(w0,  xv, pacc[256]);
            pacc[512] = fmaf(w1,  xv, pacc[512]);
            pacc[768] = fmaf(w2,  xv, pacc[768]);
        }
    }

    __syncthreads();

    // ---- block reduction: fold 28 rows -> 24 bins, write transposed partials ----
    const int bx = blockIdx.x;
    for (int p2 = tid; p2 < NR * NZ; p2 += 256) {
        const int zz = p2 & 15;
        const int rr = p2 >> 4;          // bin 0..23
        float s = 0.0f;
        #pragma unroll
        for (int j = 0; j < 16; j++) s += sm[rr + 1][zz + 16 * j];
        if (rr < 3) {                    // bins 24,25,26 wrap -> 0,1,2
            #pragma unroll
            for (int j = 0; j < 16; j++) s += sm[rr + 25][zz + 16 * j];
        }
        if (rr == 23) {                  // bin -1 wraps -> 23
            #pragma unroll
            for (int j = 0; j < 16; j++) s += sm[0][zz + 16 * j];
        }
        g_partial[(size_t)(((bf * NR + rr) * NZ) + zz) * NBLK + bx] = s;
    }
}

// One warp per output: 32 lanes x float4 = 128 contiguous partials.
__global__ __launch_bounds__(256)
void gre_finalize_kernel(float* __restrict__ out) {
    const int warp = (blockIdx.x * 256 + threadIdx.x) >> 5;   // 0..1535
    const int lane = threadIdx.x & 31;
    if (warp >= NOUT) return;
    const float4 v = ((const float4*)(g_partial + (size_t)warp * NBLK))[lane];
    float s = (v.x + v.y) + (v.z + v.w);
    #pragma unroll
    for (int o = 16; o > 0; o >>= 1) s += __shfl_down_sync(0xffffffffu, s, o);
    if (lane == 0) out[warp] = sqrtf(7.9788456080286535f * s);
}

extern "C" void kernel_launch(void* const* d_in, const int* in_sizes, int n_in,
                              void* d_out, int out_size) {
    const float* x     = (const float*)d_in[0];
    const float* com_r = (const float*)d_in[1];
    const float* com_i = (const float*)d_in[2];
    float* out = (float*)d_out;

    dim3 grid(NX / XT, NBF);
    gre_accum_kernel<<<grid, 256>>>(x, com_r, com_i);
    gre_finalize_kernel<<<NOUT / 8, 256>>>(out);
}